// round 16
// baseline (speedup 1.0000x reference)
#include <cuda_runtime.h>
#include <cuda_bf16.h>

#define DD     128
#define GATES  512
#define BATCH  64
#define NVAR   32
#define LSEQ   128
#define BSUB   16
#define PSPLIT 4

#define PRED_OFF   260096
#define CSTAR_OFF  262144

#define NW     8          // warps per CTA
#define MT     4          // m-tiles per warp
#define KT9    9          // k-tiles (8 real + 1 for x/bias)
#define HSTR   76         // u32 words per hbuf row (152 bf16; k 0..151)
#define HBUF_W (8 * HSTR) // words per (group,par,hl) buffer: 8 rows
#define HBUF_B (HBUF_W * 4)

typedef unsigned long long u64;
typedef unsigned u32;

// ---------------- device scratch ----------------
__device__ __align__(16) uint4 g_AhiE[NVAR * NW * MT * KT9 * 32];
__device__ __align__(16) uint4 g_AloE[NVAR * NW * MT * KT9 * 32];
__device__ __align__(16) uint4 g_AhiD[NVAR * NW * MT * KT9 * 32];
__device__ __align__(16) uint4 g_AloD[NVAR * NW * MT * KT9 * 32];
__device__ __align__(16) float g_WqkvT[DD * 384];
__device__ __align__(16) float g_C    [BATCH * NVAR * DD];
__device__ __align__(16) float g_Cstar[BATCH * NVAR * DD];

// ---------------- scalar helpers ----------------
__device__ __forceinline__ u64 ffma2(u64 a, u64 b, u64 c) {
    u64 d; asm("fma.rn.f32x2 %0, %1, %2, %3;" : "=l"(d) : "l"(a), "l"(b), "l"(c)); return d;
}
__device__ __forceinline__ u64 pack2(float lo, float hi) {
    u64 r; asm("mov.b64 %0, {%1, %2};" : "=l"(r) : "f"(lo), "f"(hi)); return r;
}
__device__ __forceinline__ void unpack2(u64 v, float& lo, float& hi) {
    asm("mov.b64 {%0, %1}, %2;" : "=f"(lo), "=f"(hi) : "l"(v));
}
__device__ __forceinline__ float fsig(float x)  { return __fdividef(1.f, 1.f + __expf(-x)); }
__device__ __forceinline__ float ftanhf(float x){ return 1.f - __fdividef(2.f, __expf(2.f * x) + 1.f); }
__device__ __forceinline__ u32 smem_u32(const void* p) { return (u32)__cvta_generic_to_shared(p); }

__device__ __forceinline__ unsigned short f2bf(float x) {
    __nv_bfloat16 b = __float2bfloat16(x); return *(unsigned short*)&b;
}
__device__ __forceinline__ float bf2f(unsigned short s) {
    u32 v = ((u32)s) << 16; float f; asm("mov.b32 %0, %1;" : "=f"(f) : "r"(v)); return f;
}

__device__ __forceinline__ void mbar_init(u32 m, u32 c) {
    asm volatile("mbarrier.init.shared.b64 [%0], %1;" :: "r"(m), "r"(c) : "memory");
}
__device__ __forceinline__ void mbar_expect_tx(u32 m, u32 b) {
    asm volatile("mbarrier.arrive.expect_tx.shared.b64 _, [%0], %1;" :: "r"(m), "r"(b) : "memory");
}
__device__ __forceinline__ void mbar_wait(u32 m, u32 ph) {
    u32 done;
    asm volatile("{\n\t.reg .pred p;\n\t"
        "mbarrier.try_wait.parity.acquire.cta.shared::cta.b64 p, [%1], %2;\n\t"
        "selp.b32 %0, 1, 0, p;\n\t}" : "=r"(done) : "r"(m), "r"(ph) : "memory");
    if (!done) {
        asm volatile("{\n\t.reg .pred P1;\n\t"
            "W_%=:\n\t"
            "mbarrier.try_wait.parity.acquire.cta.shared::cta.b64 P1, [%0], %1, 0x989680;\n\t"
            "@P1 bra.uni DN_%=;\n\tbra.uni W_%=;\n\tDN_%=:\n\t}"
            :: "r"(m), "r"(ph) : "memory");
    }
}
__device__ __forceinline__ void bulk_copy(const void* g, void* s, u32 bytes, u32 m) {
    asm volatile(
        "cp.async.bulk.shared::cluster.global.mbarrier::complete_tx::bytes [%0], [%1], %2, [%3];"
        :: "r"(smem_u32(s)), "l"(g), "r"(bytes), "r"(m) : "memory");
}

// NON-volatile: pure register op — lets ptxas interleave HMMA issue with the
// other group's MUFU/FMA epilogue (the R14 pipeline was serialized by volatile).
__device__ __forceinline__ void mma16816(float* d, const u32* a, const u32* b) {
    asm("mma.sync.aligned.m16n8k16.row.col.f32.bf16.bf16.f32 "
        "{%0,%1,%2,%3}, {%4,%5,%6,%7}, {%8,%9}, {%0,%1,%2,%3};"
        : "+f"(d[0]), "+f"(d[1]), "+f"(d[2]), "+f"(d[3])
        : "r"(a[0]), "r"(a[1]), "r"(a[2]), "r"(a[3]), "r"(b[0]), "r"(b[1]));
}

// ---------------- SMEM ----------------
struct __align__(16) SmemMMA {
    uint4 alo[NW * MT * KT9 * 32];     // 147456 B
    u32   hbuf[8][HBUF_W];             // [g*4+par*2+hl][8 rows x 76 words] = 19456 B
    float xs[2048];                    // enc: x[t][b]; dec: cs[k][b]
    float sp[NW][16];                  // 512 B
    u64   mbar[2];
};
#define SMEM_MMA ((int)sizeof(SmemMMA))

// ---------------- weight pack ----------------
__global__ void pack_w(const float* __restrict__ W, const float* __restrict__ Wih,
                       const float* __restrict__ bih, const float* __restrict__ bhh,
                       uint4* __restrict__ Ahi, uint4* __restrict__ Alo, int has_x) {
    int idx = blockIdx.x * 256 + threadIdx.x;
    int lane = idx & 31;
    int kt   = (idx >> 5) % 9;
    int rest = (idx >> 5) / 9;
    int mt   = rest & 3;
    int w    = (rest >> 2) & 7;
    int n    = rest >> 5;
    int gid = lane >> 2, t = lane & 3;
    u32 hi[4], lo[4];
    #pragma unroll
    for (int rr = 0; rr < 4; rr++) {
        int row   = (rr & 1) ? gid + 8 : gid;
        int cbase = (rr >> 1) ? 2 * t + 8 : 2 * t;
        int u    = 16 * w + ((mt >> 1) << 3) + (row & 7);
        int gate = ((mt & 1) << 1) + (row >> 3);
        u32 hv = 0, lv = 0;
        #pragma unroll
        for (int e = 0; e < 2; e++) {
            int col = cbase + e;
            unsigned short hb = 0, lb = 0;
            if (kt < 8) {
                float v = W[((size_t)n * GATES + gate * 128 + u) * DD + kt * 16 + col];
                hb = f2bf(v);
                lb = f2bf(v - bf2f(hb));
            } else {
                if (col == 0 || col == 1) {
                    float wv = has_x ? Wih[(size_t)n * GATES + gate * 128 + u] : 0.f;
                    unsigned short wh = f2bf(wv);
                    hb = (col == 0) ? wh : f2bf(wv - bf2f(wh));
                } else if (col == 2 || col == 3) {
                    float bv = bih[(size_t)n * GATES + gate * 128 + u]
                             + bhh[(size_t)n * GATES + gate * 128 + u];
                    unsigned short bh16 = f2bf(bv);
                    hb = (col == 2) ? bh16 : f2bf(bv - bf2f(bh16));
                }
                lb = 0;
            }
            hv |= ((u32)hb) << (16 * e);
            lv |= ((u32)lb) << (16 * e);
        }
        hi[rr] = hv; lo[rr] = lv;
    }
    Ahi[idx] = make_uint4(hi[0], hi[1], hi[2], hi[3]);
    Alo[idx] = make_uint4(lo[0], lo[1], lo[2], lo[3]);
}

__global__ void transpose_kernel(const float* __restrict__ src, float* __restrict__ dst, int R, int C) {
    __shared__ float tile[32][33];
    int c0 = blockIdx.x * 32, r0 = blockIdx.y * 32;
    #pragma unroll
    for (int i = threadIdx.y; i < 32; i += 8)
        tile[i][threadIdx.x] = src[(r0 + i) * C + c0 + threadIdx.x];
    __syncthreads();
    #pragma unroll
    for (int i = threadIdx.y; i < 32; i += 8)
        dst[(c0 + i) * R + r0 + threadIdx.x] = tile[threadIdx.x][i];
}

// ---------------- per-group GEMM: acc[4][4] += W x h_g (3-term bf16 split) ----------------
__device__ __forceinline__ void do_mma_g(
    const uint4* __restrict__ aloW, const u32* __restrict__ hb,
    const u32* __restrict__ ahi, float acc[4][4], int lane)
{
    int gid = lane >> 2, t = lane & 3;
    int bo = gid * HSTR + t;
    const u32* hl = hb + HBUF_W;
    #pragma unroll
    for (int kt = 0; kt < KT9; kt++) {
        int wo = kt * 8;
        u32 bh[2] = { hb[bo + wo], hb[bo + wo + 4] };
        u32 bl[2] = { hl[bo + wo], hl[bo + wo + 4] };
        #pragma unroll
        for (int mt = 0; mt < 4; mt++) {
            const u32* ah = ahi + (mt * KT9 + kt) * 4;
            mma16816(acc[mt], ah, bh);
            mma16816(acc[mt], ah, bl);
            if (kt < 8) {
                uint4 v = aloW[(mt * KT9 + kt) * 32 + lane];
                u32 al[4] = {v.x, v.y, v.z, v.w};
                mma16816(acc[mt], al, bh);
            }
        }
    }
}

__device__ __forceinline__ void gates_group(const float acc[4][4], float c[2][2], float h[2][2]) {
    #pragma unroll
    for (int ui = 0; ui < 2; ui++) {
        int mb = 2 * ui;
        #pragma unroll
        for (int j = 0; j < 2; j++) {
            float pi = acc[mb][j],     pf = acc[mb][2 + j];
            float pg = acc[mb + 1][j], po = acc[mb + 1][2 + j];
            float cn = fsig(pf) * c[ui][j] + fsig(pi) * ftanhf(pg);
            c[ui][j] = cn;
            h[ui][j] = fsig(po) * ftanhf(cn);
        }
    }
}

__device__ __forceinline__ void store_hv(u32 hibase, int cg, int u, float h) {
    u32 byte = (u32)(cg * HSTR + (u >> 1)) * 4 + (u & 1) * 2;
    unsigned short hb = f2bf(h);
    unsigned short lb = f2bf(h - bf2f(hb));
    asm volatile("st.shared.b16 [%0], %1;" :: "r"(hibase + byte), "h"(hb) : "memory");
    asm volatile("st.shared.b16 [%0], %1;" :: "r"(hibase + HBUF_B + byte), "h"(lb) : "memory");
}
__device__ __forceinline__ void store_group(u32 hibase, const float h[2][2], int t, int u0, int u1) {
    #pragma unroll
    for (int j = 0; j < 2; j++) {
        store_hv(hibase, 2 * t + j, u0, h[0][j]);
        store_hv(hibase, 2 * t + j, u1, h[1][j]);
    }
}

// ================= encoder =================
__global__ __launch_bounds__(256, 1) void enc_kernel(
    const float* __restrict__ X,
    const float* __restrict__ pool_w, const float* __restrict__ pool_b) {
    extern __shared__ __align__(16) char smraw[];
    SmemMMA* sm = (SmemMMA*)smraw;
    const int nv = blockIdx.y, p = blockIdx.x;
    const int tid = threadIdx.x, lane = tid & 31, w = tid >> 5;
    const int gid = lane >> 2, t = lane & 3;
    u32 mbA = smem_u32(&sm->mbar[0]);

    if (tid == 0) {
        mbar_init(mbA, 1);
        mbar_expect_tx(mbA, 147456);
        const char* src = (const char*)(g_AloE + (size_t)nv * (NW * MT * KT9 * 32));
        bulk_copy(src,          sm->alo,                 73728, mbA);
        bulk_copy(src + 73728, (char*)sm->alo + 73728,   73728, mbA);
    }
    for (int i = tid; i < 8 * HBUF_W; i += 256) ((u32*)sm->hbuf)[i] = 0;
    for (int i = tid; i < 2048; i += 256) {
        int b = i & 15, tt = i >> 4;
        sm->xs[i] = X[((size_t)(p * BSUB + b) * LSEQ + tt) * NVAR + nv];
    }
    u32 ahi[MT * KT9 * 4];
    {
        const uint4* gA = g_AhiE + ((size_t)nv * NW + w) * (MT * KT9 * 32);
        #pragma unroll
        for (int f = 0; f < MT * KT9; f++) {
            uint4 v = gA[f * 32 + lane];
            ahi[f * 4] = v.x; ahi[f * 4 + 1] = v.y; ahi[f * 4 + 2] = v.z; ahi[f * 4 + 3] = v.w;
        }
    }
    __syncthreads();
    if (tid < 32) {
        int g = tid >> 4, par = (tid >> 3) & 1, row = tid & 7;
        sm->hbuf[(g << 2) | (par << 1)][row * HSTR + 65] = 0x3F803F80u;
    }
    if (tid < 16) {
        int g = tid >> 3, row = tid & 7;
        float x = sm->xs[tid];
        unsigned short xh = f2bf(x);
        unsigned short xl = f2bf(x - bf2f(xh));
        sm->hbuf[(g << 2)][row * HSTR + 64]     = (u32)xh | ((u32)xh << 16);
        sm->hbuf[(g << 2) | 1][row * HSTR + 64] = (u32)xl;
    }
    mbar_wait(mbA, 0);
    __syncthreads();

    const int u0 = 16 * w + gid, u1 = u0 + 8;
    const float pw0 = pool_w[nv * DD + u0], pw1 = pool_w[nv * DD + u1];
    const float pb = pool_b[nv];
    float cA[2][2], cB[2][2], hA[2][2], hB[2][2];
    float accCA[2][2], accCB[2][2], pmA[2], pmB[2], psA[2], psB[2];
    #pragma unroll
    for (int ui = 0; ui < 2; ui++)
        #pragma unroll
        for (int j = 0; j < 2; j++) {
            cA[ui][j] = cB[ui][j] = 0.f;
            accCA[ui][j] = accCB[ui][j] = 0.f;
        }
    #pragma unroll
    for (int j = 0; j < 2; j++) { pmA[j] = pmB[j] = -1e30f; psA[j] = psB[j] = 0.f; }

    const uint4* aloW = sm->alo + w * (MT * KT9 * 32);
    float accA[4][4], accB[4][4];
    #pragma unroll
    for (int m = 0; m < 4; m++)
        #pragma unroll
        for (int r = 0; r < 4; r++) accA[m][r] = 0.f;
    do_mma_g(aloW, sm->hbuf[0], ahi, accA, lane);

    const int TS = LSEQ - 1;
    for (int ts = 0; ts < TS; ts++) {
        int par = ts & 1;
        #pragma unroll
        for (int m = 0; m < 4; m++)
            #pragma unroll
            for (int r = 0; r < 4; r++) accB[m][r] = 0.f;
        do_mma_g(aloW, sm->hbuf[4 | (par << 1)], ahi, accB, lane);
        gates_group(accA, cA, hA);
        u32 hibA = smem_u32(sm->hbuf[(par ^ 1) << 1]);
        store_group(hibA, hA, t, u0, u1);
        if (tid < 8 && ts + 1 < LSEQ) {
            float x = sm->xs[(ts + 1) * 16 + tid];
            unsigned short xh = f2bf(x);
            unsigned short xl = f2bf(x - bf2f(xh));
            sm->hbuf[(par ^ 1) << 1][tid * HSTR + 64]       = (u32)xh | ((u32)xh << 16);
            sm->hbuf[((par ^ 1) << 1) | 1][tid * HSTR + 64] = (u32)xl;
        }
        {
            float part[2];
            #pragma unroll
            for (int j = 0; j < 2; j++) part[j] = hA[0][j] * pw0 + hA[1][j] * pw1;
            #pragma unroll
            for (int off = 4; off <= 16; off <<= 1)
                #pragma unroll
                for (int j = 0; j < 2; j++)
                    part[j] += __shfl_xor_sync(0xffffffffu, part[j], off);
            if (gid == 0) { sm->sp[w][2 * t] = part[0]; sm->sp[w][2 * t + 1] = part[1]; }
        }
        __syncthreads();
        #pragma unroll
        for (int j = 0; j < 2; j++) {
            float s = pb;
            #pragma unroll
            for (int ww = 0; ww < NW; ww++) s += sm->sp[ww][2 * t + j];
            float mn = fmaxf(pmA[j], s);
            float scale = __expf(pmA[j] - mn);
            float wcur  = __expf(s - mn);
            psA[j] = psA[j] * scale + wcur;
            pmA[j] = mn;
            accCA[0][j] = accCA[0][j] * scale + wcur * hA[0][j];
            accCA[1][j] = accCA[1][j] * scale + wcur * hA[1][j];
        }
        if (ts + 1 < TS) {
            #pragma unroll
            for (int m = 0; m < 4; m++)
                #pragma unroll
                for (int r = 0; r < 4; r++) accA[m][r] = 0.f;
            do_mma_g(aloW, sm->hbuf[(par ^ 1) << 1], ahi, accA, lane);
        }
        gates_group(accB, cB, hB);
        u32 hibB = smem_u32(sm->hbuf[4 | ((par ^ 1) << 1)]);
        store_group(hibB, hB, t, u0, u1);
        if (tid >= 8 && tid < 16 && ts + 1 < LSEQ) {
            float x = sm->xs[(ts + 1) * 16 + tid];
            unsigned short xh = f2bf(x);
            unsigned short xl = f2bf(x - bf2f(xh));
            sm->hbuf[4 | ((par ^ 1) << 1)][(tid - 8) * HSTR + 64]       = (u32)xh | ((u32)xh << 16);
            sm->hbuf[4 | ((par ^ 1) << 1) | 1][(tid - 8) * HSTR + 64]   = (u32)xl;
        }
        {
            float part[2];
            #pragma unroll
            for (int j = 0; j < 2; j++) part[j] = hB[0][j] * pw0 + hB[1][j] * pw1;
            #pragma unroll
            for (int off = 4; off <= 16; off <<= 1)
                #pragma unroll
                for (int j = 0; j < 2; j++)
                    part[j] += __shfl_xor_sync(0xffffffffu, part[j], off);
            if (gid == 0) { sm->sp[w][8 + 2 * t] = part[0]; sm->sp[w][8 + 2 * t + 1] = part[1]; }
        }
        __syncthreads();
        #pragma unroll
        for (int j = 0; j < 2; j++) {
            float s = pb;
            #pragma unroll
            for (int ww = 0; ww < NW; ww++) s += sm->sp[ww][8 + 2 * t + j];
            float mn = fmaxf(pmB[j], s);
            float scale = __expf(pmB[j] - mn);
            float wcur  = __expf(s - mn);
            psB[j] = psB[j] * scale + wcur;
            pmB[j] = mn;
            accCB[0][j] = accCB[0][j] * scale + wcur * hB[0][j];
            accCB[1][j] = accCB[1][j] * scale + wcur * hB[1][j];
        }
    }
    #pragma unroll
    for (int j = 0; j < 2; j++) {
        int bA = p * BSUB + 2 * t + j;
        int bB = bA + 8;
        float ivA = __fdividef(1.f, psA[j]);
        float ivB = __fdividef(1.f, psB[j]);
        g_C[((size_t)bA * NVAR + nv) * DD + u0] = accCA[0][j] * ivA;
        g_C[((size_t)bA * NVAR + nv) * DD + u1] = accCA[1][j] * ivA;
        g_C[((size_t)bB * NVAR + nv) * DD + u0] = accCB[0][j] * ivB;
        g_C[((size_t)bB * NVAR + nv) * DD + u1] = accCB[1][j] * ivB;
    }
}

// ================= MHSA =================
__global__ __launch_bounds__(128, 1) void mhsa_kernel(
    const float* __restrict__ bqkv,
    const float* __restrict__ Wo, const float* __restrict__ bo,
    float* __restrict__ out) {
    extern __shared__ __align__(16) float smf[];
    float* Cs  = smf;
    float* QKV = smf + 4352;
    float* As  = smf;
    const int b = blockIdx.x, tid = threadIdx.x;

    #pragma unroll 4
    for (int i = 0; i < 32; i++)
        Cs[tid * 34 + i] = g_C[(b * NVAR + i) * DD + tid];
    __syncthreads();

    for (int jj = 0; jj < 3; jj++) {
        int j = jj * 128 + tid;
        float bj = bqkv[j];
        u64 acc[16];
        #pragma unroll
        for (int vp = 0; vp < 16; vp++) acc[vp] = pack2(bj, bj);
        #pragma unroll 2
        for (int k = 0; k < DD; k++) {
            float wv = g_WqkvT[k * 384 + j];
            u64 ww = pack2(wv, wv);
            const u64* crow = (const u64*)&Cs[k * 34];
            #pragma unroll
            for (int vp = 0; vp < 16; vp++) acc[vp] = ffma2(ww, crow[vp], acc[vp]);
        }
        #pragma unroll
        for (int vp = 0; vp < 16; vp++) {
            float a0, a1; unpack2(acc[vp], a0, a1);
            QKV[(2 * vp)     * 385 + j] = a0;
            QKV[(2 * vp + 1) * 385 + j] = a1;
        }
    }
    __syncthreads();
    {
        int h = tid >> 5, i = tid & 31;
        float q[32];
        #pragma unroll
        for (int d = 0; d < 32; d++) q[d] = QKV[i * 385 + h * 32 + d];
        float s[32];
        #pragma unroll
        for (int j = 0; j < 32; j++) {
            float a = 0.f;
            #pragma unroll
            for (int d = 0; d < 32; d++) a += q[d] * QKV[j * 385 + 128 + h * 32 + d];
            s[j] = a * 0.17677669529663687f;
        }
        float mx = s[0];
        #pragma unroll
        for (int j = 1; j < 32; j++) mx = fmaxf(mx, s[j]);
        float sum = 0.f;
        #pragma unroll
        for (int j = 0; j < 32; j++) { s[j] = __expf(s[j] - mx); sum += s[j]; }
        float inv = __fdividef(1.f, sum);
        float A[32];
        #pragma unroll
        for (int d = 0; d < 32; d++) A[d] = 0.f;
        #pragma unroll
        for (int j = 0; j < 32; j++) {
            float aj = s[j] * inv;
            #pragma unroll
            for (int d = 0; d < 32; d++) A[d] += aj * QKV[j * 385 + 256 + h * 32 + d];
        }
        #pragma unroll
        for (int d = 0; d < 32; d++) As[i * 129 + h * 32 + d] = A[d];
    }
    __syncthreads();
    {
        int v = tid & 31, uc = tid >> 5;
        for (int mm = 0; mm < 32; mm++) {
            int u = uc * 32 + mm;
            float a = bo[u];
            #pragma unroll 4
            for (int d = 0; d < DD; d++) a += As[v * 129 + d] * Wo[u * DD + d];
            g_Cstar[(b * NVAR + v) * DD + u] = a;
            out[CSTAR_OFF + (b * NVAR + v) * DD + u] = a;
        }
    }
}

// ================= decoder =================
__global__ __launch_bounds__(256, 1) void dec_kernel(
    const float* __restrict__ ihW, const float* __restrict__ ihB,
    const float* __restrict__ icW, const float* __restrict__ icB,
    const float* __restrict__ outW, const float* __restrict__ outB,
    float* __restrict__ out) {
    extern __shared__ __align__(16) char smraw[];
    SmemMMA* sm = (SmemMMA*)smraw;
    const int nv = blockIdx.y, p = blockIdx.x;
    const int tid = threadIdx.x, lane = tid & 31, w = tid >> 5;
    const int gid = lane >> 2, t = lane & 3;
    u32 mbA = smem_u32(&sm->mbar[0]);

    if (tid == 0) {
        mbar_init(mbA, 1);
        mbar_expect_tx(mbA, 147456);
        const char* src = (const char*)(g_AloD + (size_t)nv * (NW * MT * KT9 * 32));
        bulk_copy(src,          sm->alo,                73728, mbA);
        bulk_copy(src + 73728, (char*)sm->alo + 73728,  73728, mbA);
    }
    for (int i = tid; i < 8 * HBUF_W; i += 256) ((u32*)sm->hbuf)[i] = 0;
    for (int i = tid; i < 2048; i += 256) {
        int b = i & 15, k = i >> 4;
        sm->xs[i] = g_Cstar[((size_t)(p * BSUB + b) * NVAR + nv) * DD + k];
    }
    u32 ahi[MT * KT9 * 4];
    {
        const uint4* gA = g_AhiD + ((size_t)nv * NW + w) * (MT * KT9 * 32);
        #pragma unroll
        for (int f = 0; f < MT * KT9; f++) {
            uint4 v = gA[f * 32 + lane];
            ahi[f * 4] = v.x; ahi[f * 4 + 1] = v.y; ahi[f * 4 + 2] = v.z; ahi[f * 4 + 3] = v.w;
        }
    }
    __syncthreads();
    if (tid < 32) {
        int g = tid >> 4, par = (tid >> 3) & 1, row = tid & 7;
        sm->hbuf[(g << 2) | (par << 1)][row * HSTR + 65] = 0x3F803F80u;
    }

    const int u0 = 16 * w + gid, u1 = u0 + 8;
    int gcols[4] = {2 * t, 2 * t + 1, 8 + 2 * t, 8 + 2 * t + 1};

    float cA[2][2], cB[2][2], hA[2][2], hB[2][2];
    {
        float ah0[4], ah1[4], ac0[4], ac1[4];
        float bh0 = ihB[nv * DD + u0], bh1 = ihB[nv * DD + u1];
        float bc0 = icB[nv * DD + u0], bc1 = icB[nv * DD + u1];
        #pragma unroll
        for (int j = 0; j < 4; j++) { ah0[j] = bh0; ah1[j] = bh1; ac0[j] = bc0; ac1[j] = bc1; }
        const float* wh0 = ihW + ((size_t)nv * DD + u0) * DD;
        const float* wh1 = ihW + ((size_t)nv * DD + u1) * DD;
        const float* wc0 = icW + ((size_t)nv * DD + u0) * DD;
        const float* wc1 = icW + ((size_t)nv * DD + u1) * DD;
        #pragma unroll 2
        for (int k = 0; k < DD; k++) {
            float a0 = wh0[k], a1 = wh1[k], b0 = wc0[k], b1 = wc1[k];
            #pragma unroll
            for (int j = 0; j < 4; j++) {
                float cv = sm->xs[k * 16 + gcols[j]];
                ah0[j] += a0 * cv; ah1[j] += a1 * cv;
                ac0[j] += b0 * cv; ac1[j] += b1 * cv;
            }
        }
        #pragma unroll
        for (int j = 0; j < 2; j++) {
            hA[0][j] = ftanhf(ah0[j]);     hA[1][j] = ftanhf(ah1[j]);
            cA[0][j] = ftanhf(ac0[j]);     cA[1][j] = ftanhf(ac1[j]);
            hB[0][j] = ftanhf(ah0[2 + j]); hB[1][j] = ftanhf(ah1[2 + j]);
            cB[0][j] = ftanhf(ac0[2 + j]); cB[1][j] = ftanhf(ac1[2 + j]);
        }
    }
    __syncthreads();
    store_group(smem_u32(sm->hbuf[0]), hA, t, u0, u1);
    store_group(smem_u32(sm->hbuf[4]), hB, t, u0, u1);
    mbar_wait(mbA, 0);
    __syncthreads();

    const float wo0 = outW[nv * DD + u0], wo1 = outW[nv * DD + u1];
    const float ob = outB[nv];
    const uint4* aloW = sm->alo + w * (MT * KT9 * 32);
    const int b_row0 = p * BSUB;

    float accA[4][4], accB[4][4];
    #pragma unroll
    for (int m = 0; m < 4; m++)
        #pragma unroll
        for (int r = 0; r < 4; r++) accA[m][r] = 0.f;
    do_mma_g(aloW, sm->hbuf[0], ahi, accA, lane);

    for (int l = 0; l < LSEQ; l++) {
        int par = l & 1;
        #pragma unroll
        for (int m = 0; m < 4; m++)
            #pragma unroll
            for (int r = 0; r < 4; r++) accB[m][r] = 0.f;
        do_mma_g(aloW, sm->hbuf[4 | (par << 1)], ahi, accB, lane);

        gates_group(accA, cA, hA);
        store_group(smem_u32(sm->hbuf[(par ^ 1) << 1]), hA, t, u0, u1);
        {
            float part[2];
            #pragma unroll
            for (int j = 0; j < 2; j++) part[j] = hA[0][j] * wo0 + hA[1][j] * wo1;
            #pragma unroll
            for (int off = 4; off <= 16; off <<= 1)
                #pragma unroll
                for (int j = 0; j < 2; j++)
                    part[j] += __shfl_xor_sync(0xffffffffu, part[j], off);
            if (gid == 0) { sm->sp[w][2 * t] = part[0]; sm->sp[w][2 * t + 1] = part[1]; }
        }
        __syncthreads();
        if (tid < 8) {
            float O = ob;
            #pragma unroll
            for (int ww = 0; ww < NW; ww++) O += sm->sp[ww][tid];
            int b = b_row0 + tid;
            if (l < LSEQ - 1) out[((size_t)b * (LSEQ - 1) + l) * NVAR + nv] = O;
            else              out[PRED_OFF + b * NVAR + nv] = O;
        }
        if (l + 1 < LSEQ) {
            #pragma unroll
            for (int m = 0; m < 4; m++)
                #pragma unroll
                for (int r = 0; r < 4; r++) accA[m][r] = 0.f;
            do_mma_g(aloW, sm->hbuf[(par ^ 1) << 1], ahi, accA, lane);
        }
        gates_group(accB, cB, hB);
        store_group(smem_u32(sm->hbuf[4 | ((par ^ 1) << 1)]), hB, t, u0, u1);
        {
            float part[2];
            #pragma unroll
            for (int j = 0; j < 2; j++) part[j] = hB[0][j] * wo0 + hB[1][j] * wo1;
            #pragma unroll
            for (int off = 4; off <= 16; off <<= 1)
                #pragma unroll
                for (int j = 0; j < 2; j++)
                    part[j] += __shfl_xor_sync(0xffffffffu, part[j], off);
            if (gid == 0) { sm->sp[w][8 + 2 * t] = part[0]; sm->sp[w][8 + 2 * t + 1] = part[1]; }
        }
        __syncthreads();
        if (tid >= 8 && tid < 16) {
            float O = ob;
            #pragma unroll
            for (int ww = 0; ww < NW; ww++) O += sm->sp[ww][tid];
            int b = b_row0 + tid;
            if (l < LSEQ - 1) out[((size_t)b * (LSEQ - 1) + l) * NVAR + nv] = O;
            else              out[PRED_OFF + b * NVAR + nv] = O;
        }
    }
}

// ---------------- launch ----------------
extern "C" void kernel_launch(void* const* d_in, const int* in_sizes, int n_in,
                              void* d_out, int out_size) {
    (void)in_sizes; (void)n_in; (void)out_size;
    const float* X        = (const float*)d_in[0];
    const float* enc_Wih  = (const float*)d_in[1];
    const float* enc_Whh  = (const float*)d_in[2];
    const float* enc_bih  = (const float*)d_in[3];
    const float* enc_bhh  = (const float*)d_in[4];
    const float* pool_w   = (const float*)d_in[5];
    const float* pool_b   = (const float*)d_in[6];
    const float* Wqkv     = (const float*)d_in[7];
    const float* bqkv     = (const float*)d_in[8];
    const float* Wo       = (const float*)d_in[9];
    const float* bo       = (const float*)d_in[10];
    const float* dec_ih_W = (const float*)d_in[11];
    const float* dec_ih_b = (const float*)d_in[12];
    const float* dec_ic_W = (const float*)d_in[13];
    const float* dec_ic_b = (const float*)d_in[14];
    const float* dec_Wih  = (const float*)d_in[15];
    const float* dec_Whh  = (const float*)d_in[16];
    const float* dec_bih  = (const float*)d_in[17];
    const float* dec_bhh  = (const float*)d_in[18];
    const float* dec_out_W= (const float*)d_in[19];
    const float* dec_out_b= (const float*)d_in[20];
    float* out = (float*)d_out;

    static int attr_set = 0;
    if (!attr_set) {
        cudaFuncSetAttribute(mhsa_kernel, cudaFuncAttributeMaxDynamicSharedMemorySize, 66688);
        cudaFuncSetAttribute(enc_kernel,  cudaFuncAttributeMaxDynamicSharedMemorySize, SMEM_MMA);
        cudaFuncSetAttribute(dec_kernel,  cudaFuncAttributeMaxDynamicSharedMemorySize, SMEM_MMA);
        attr_set = 1;
    }

    uint4 *pAhiE, *pAloE, *pAhiD, *pAloD; float* pWqkvT;
    cudaGetSymbolAddress((void**)&pAhiE, g_AhiE);
    cudaGetSymbolAddress((void**)&pAloE, g_AloE);
    cudaGetSymbolAddress((void**)&pAhiD, g_AhiD);
    cudaGetSymbolAddress((void**)&pAloD, g_AloD);
    cudaGetSymbolAddress((void**)&pWqkvT, g_WqkvT);

    pack_w<<<1152, 256>>>(enc_Whh, enc_Wih, enc_bih, enc_bhh, pAhiE, pAloE, 1);
    pack_w<<<1152, 256>>>(dec_Whh, dec_Wih, dec_bih, dec_bhh, pAhiD, pAloD, 0);
    transpose_kernel<<<dim3(4, 12, 1), dim3(32, 8)>>>(Wqkv, pWqkvT, 384, 128);

    enc_kernel<<<dim3(PSPLIT, NVAR), 256, SMEM_MMA>>>(X, pool_w, pool_b);
    mhsa_kernel<<<BATCH, 128, 66688>>>(bqkv, Wo, bo, out);
    dec_kernel<<<dim3(PSPLIT, NVAR), 256, SMEM_MMA>>>(dec_ih_W, dec_ih_b, dec_ic_W, dec_ic_b,
                                                      dec_out_W, dec_out_b, out);
}

// round 17
// speedup vs baseline: 1.0993x; 1.0993x over previous
#include <cuda_runtime.h>
#include <cuda_bf16.h>

#define DD     128
#define GATES  512
#define BATCH  64
#define NVAR   32
#define LSEQ   128
#define BSUB   16
#define PSPLIT 4

#define PRED_OFF   260096
#define CSTAR_OFF  262144

#define NW     8          // warps per CTA
#define MT     4          // m-tiles per warp
#define KT9    9          // k-tiles (8 real + 1 for x/bias)
#define HSTR   76         // u32 words per hbuf row (152 bf16; k 0..151)
#define HBUF_W (8 * HSTR) // words per (group,par,hl) buffer: 8 rows
#define HBUF_B (HBUF_W * 4)

typedef unsigned long long u64;
typedef unsigned u32;

// ---------------- device scratch ----------------
__device__ __align__(16) uint4 g_AhiE[NVAR * NW * MT * KT9 * 32];
__device__ __align__(16) uint4 g_AloE[NVAR * NW * MT * KT9 * 32];
__device__ __align__(16) uint4 g_AhiD[NVAR * NW * MT * KT9 * 32];
__device__ __align__(16) uint4 g_AloD[NVAR * NW * MT * KT9 * 32];
__device__ __align__(16) float g_WqkvT[DD * 384];
__device__ __align__(16) float g_C    [BATCH * NVAR * DD];
__device__ __align__(16) float g_Cstar[BATCH * NVAR * DD];

// ---------------- scalar helpers ----------------
__device__ __forceinline__ u64 ffma2(u64 a, u64 b, u64 c) {
    u64 d; asm("fma.rn.f32x2 %0, %1, %2, %3;" : "=l"(d) : "l"(a), "l"(b), "l"(c)); return d;
}
__device__ __forceinline__ u64 pack2(float lo, float hi) {
    u64 r; asm("mov.b64 %0, {%1, %2};" : "=l"(r) : "f"(lo), "f"(hi)); return r;
}
__device__ __forceinline__ void unpack2(u64 v, float& lo, float& hi) {
    asm("mov.b64 {%0, %1}, %2;" : "=f"(lo), "=f"(hi) : "l"(v));
}
__device__ __forceinline__ float fsig(float x)  { return __fdividef(1.f, 1.f + __expf(-x)); }
__device__ __forceinline__ float ftanhf(float x){ return 1.f - __fdividef(2.f, __expf(2.f * x) + 1.f); }
__device__ __forceinline__ u32 smem_u32(const void* p) { return (u32)__cvta_generic_to_shared(p); }

__device__ __forceinline__ unsigned short f2bf(float x) {
    __nv_bfloat16 b = __float2bfloat16(x); return *(unsigned short*)&b;
}
__device__ __forceinline__ float bf2f(unsigned short s) {
    u32 v = ((u32)s) << 16; float f; asm("mov.b32 %0, %1;" : "=f"(f) : "r"(v)); return f;
}

__device__ __forceinline__ void mbar_init(u32 m, u32 c) {
    asm volatile("mbarrier.init.shared.b64 [%0], %1;" :: "r"(m), "r"(c) : "memory");
}
__device__ __forceinline__ void mbar_expect_tx(u32 m, u32 b) {
    asm volatile("mbarrier.arrive.expect_tx.shared.b64 _, [%0], %1;" :: "r"(m), "r"(b) : "memory");
}
__device__ __forceinline__ void mbar_wait(u32 m, u32 ph) {
    u32 done;
    asm volatile("{\n\t.reg .pred p;\n\t"
        "mbarrier.try_wait.parity.acquire.cta.shared::cta.b64 p, [%1], %2;\n\t"
        "selp.b32 %0, 1, 0, p;\n\t}" : "=r"(done) : "r"(m), "r"(ph) : "memory");
    if (!done) {
        asm volatile("{\n\t.reg .pred P1;\n\t"
            "W_%=:\n\t"
            "mbarrier.try_wait.parity.acquire.cta.shared::cta.b64 P1, [%0], %1, 0x989680;\n\t"
            "@P1 bra.uni DN_%=;\n\tbra.uni W_%=;\n\tDN_%=:\n\t}"
            :: "r"(m), "r"(ph) : "memory");
    }
}
__device__ __forceinline__ void bulk_copy(const void* g, void* s, u32 bytes, u32 m) {
    asm volatile(
        "cp.async.bulk.shared::cluster.global.mbarrier::complete_tx::bytes [%0], [%1], %2, [%3];"
        :: "r"(smem_u32(s)), "l"(g), "r"(bytes), "r"(m) : "memory");
}

// non-volatile: pure register op, data deps via "+f" accumulators
__device__ __forceinline__ void mma16816(float* d, const u32* a, const u32* b) {
    asm("mma.sync.aligned.m16n8k16.row.col.f32.bf16.bf16.f32 "
        "{%0,%1,%2,%3}, {%4,%5,%6,%7}, {%8,%9}, {%0,%1,%2,%3};"
        : "+f"(d[0]), "+f"(d[1]), "+f"(d[2]), "+f"(d[3])
        : "r"(a[0]), "r"(a[1]), "r"(a[2]), "r"(a[3]), "r"(b[0]), "r"(b[1]));
}

// ---------------- SMEM ----------------
struct __align__(16) SmemMMA {
    uint4 alo[NW * MT * KT9 * 32];     // 147456 B
    u32   hbuf[8][HBUF_W];             // [g*4+par*2+hl][8 rows x 76 words]
    float xs[2048];                    // enc: x[t][b]; dec: cs[k][b]
    float sp[NW][16];
    u64   mbar[2];
};
#define SMEM_MMA ((int)sizeof(SmemMMA))

// ---------------- weight pack ----------------
__global__ void pack_w(const float* __restrict__ W, const float* __restrict__ Wih,
                       const float* __restrict__ bih, const float* __restrict__ bhh,
                       uint4* __restrict__ Ahi, uint4* __restrict__ Alo, int has_x) {
    int idx = blockIdx.x * 256 + threadIdx.x;
    int lane = idx & 31;
    int kt   = (idx >> 5) % 9;
    int rest = (idx >> 5) / 9;
    int mt   = rest & 3;
    int w    = (rest >> 2) & 7;
    int n    = rest >> 5;
    int gid = lane >> 2, t = lane & 3;
    u32 hi[4], lo[4];
    #pragma unroll
    for (int rr = 0; rr < 4; rr++) {
        int row   = (rr & 1) ? gid + 8 : gid;
        int cbase = (rr >> 1) ? 2 * t + 8 : 2 * t;
        int u    = 16 * w + ((mt >> 1) << 3) + (row & 7);
        int gate = ((mt & 1) << 1) + (row >> 3);
        u32 hv = 0, lv = 0;
        #pragma unroll
        for (int e = 0; e < 2; e++) {
            int col = cbase + e;
            unsigned short hb = 0, lb = 0;
            if (kt < 8) {
                float v = W[((size_t)n * GATES + gate * 128 + u) * DD + kt * 16 + col];
                hb = f2bf(v);
                lb = f2bf(v - bf2f(hb));
            } else {
                if (col == 0 || col == 1) {
                    float wv = has_x ? Wih[(size_t)n * GATES + gate * 128 + u] : 0.f;
                    unsigned short wh = f2bf(wv);
                    hb = (col == 0) ? wh : f2bf(wv - bf2f(wh));
                } else if (col == 2 || col == 3) {
                    float bv = bih[(size_t)n * GATES + gate * 128 + u]
                             + bhh[(size_t)n * GATES + gate * 128 + u];
                    unsigned short bh16 = f2bf(bv);
                    hb = (col == 2) ? bh16 : f2bf(bv - bf2f(bh16));
                }
                lb = 0;
            }
            hv |= ((u32)hb) << (16 * e);
            lv |= ((u32)lb) << (16 * e);
        }
        hi[rr] = hv; lo[rr] = lv;
    }
    Ahi[idx] = make_uint4(hi[0], hi[1], hi[2], hi[3]);
    Alo[idx] = make_uint4(lo[0], lo[1], lo[2], lo[3]);
}

__global__ void transpose_kernel(const float* __restrict__ src, float* __restrict__ dst, int R, int C) {
    __shared__ float tile[32][33];
    int c0 = blockIdx.x * 32, r0 = blockIdx.y * 32;
    #pragma unroll
    for (int i = threadIdx.y; i < 32; i += 8)
        tile[i][threadIdx.x] = src[(r0 + i) * C + c0 + threadIdx.x];
    __syncthreads();
    #pragma unroll
    for (int i = threadIdx.y; i < 32; i += 8)
        dst[(c0 + i) * R + r0 + threadIdx.x] = tile[threadIdx.x][i];
}

// ---------------- one kt chunk of the group GEMM (kt is a literal at call sites) ----------------
__device__ __forceinline__ void mma_kt(
    const uint4* __restrict__ aloW, const u32* __restrict__ hb,
    const u32* __restrict__ ahi, float acc[4][4], int lane, int kt)
{
    int gid = lane >> 2, t = lane & 3;
    int bo = gid * HSTR + t + kt * 8;
    const u32* hl = hb + HBUF_W;
    u32 bh[2] = { hb[bo], hb[bo + 4] };
    u32 bl[2] = { hl[bo], hl[bo + 4] };
    #pragma unroll
    for (int mt = 0; mt < 4; mt++) {
        const u32* ah = ahi + (mt * KT9 + kt) * 4;
        mma16816(acc[mt], ah, bh);
        mma16816(acc[mt], ah, bl);
        if (kt < 8) {
            uint4 v = aloW[(mt * KT9 + kt) * 32 + lane];
            u32 al[4] = {v.x, v.y, v.z, v.w};
            mma16816(acc[mt], al, bh);
        }
    }
}

__device__ __forceinline__ void gates_group(const float acc[4][4], float c[2][2], float h[2][2]) {
    #pragma unroll
    for (int ui = 0; ui < 2; ui++) {
        int mb = 2 * ui;
        #pragma unroll
        for (int j = 0; j < 2; j++) {
            float pi = acc[mb][j],     pf = acc[mb][2 + j];
            float pg = acc[mb + 1][j], po = acc[mb + 1][2 + j];
            float cn = fsig(pf) * c[ui][j] + fsig(pi) * ftanhf(pg);
            c[ui][j] = cn;
            h[ui][j] = fsig(po) * ftanhf(cn);
        }
    }
}

__device__ __forceinline__ void store_hv(u32 hibase, int cg, int u, float h) {
    u32 byte = (u32)(cg * HSTR + (u >> 1)) * 4 + (u & 1) * 2;
    unsigned short hb = f2bf(h);
    unsigned short lb = f2bf(h - bf2f(hb));
    asm volatile("st.shared.b16 [%0], %1;" :: "r"(hibase + byte), "h"(hb) : "memory");
    asm volatile("st.shared.b16 [%0], %1;" :: "r"(hibase + HBUF_B + byte), "h"(lb) : "memory");
}
__device__ __forceinline__ void store_group(u32 hibase, const float h[2][2], int t, int u0, int u1) {
    #pragma unroll
    for (int j = 0; j < 2; j++) {
        store_hv(hibase, 2 * t + j, u0, h[0][j]);
        store_hv(hibase, 2 * t + j, u1, h[1][j]);
    }
}

#define ZACC(a) { _Pragma("unroll") for (int m_ = 0; m_ < 4; m_++) \
                  _Pragma("unroll") for (int r_ = 0; r_ < 4; r_++) (a)[m_][r_] = 0.f; }

// ================= encoder =================
__global__ __launch_bounds__(256, 1) void enc_kernel(
    const float* __restrict__ X,
    const float* __restrict__ pool_w, const float* __restrict__ pool_b) {
    extern __shared__ __align__(16) char smraw[];
    SmemMMA* sm = (SmemMMA*)smraw;
    const int nv = blockIdx.y, p = blockIdx.x;
    const int tid = threadIdx.x, lane = tid & 31, w = tid >> 5;
    const int gid = lane >> 2, t = lane & 3;
    u32 mbA = smem_u32(&sm->mbar[0]);

    if (tid == 0) {
        mbar_init(mbA, 1);
        mbar_expect_tx(mbA, 147456);
        const char* src = (const char*)(g_AloE + (size_t)nv * (NW * MT * KT9 * 32));
        bulk_copy(src,          sm->alo,                 73728, mbA);
        bulk_copy(src + 73728, (char*)sm->alo + 73728,   73728, mbA);
    }
    for (int i = tid; i < 8 * HBUF_W; i += 256) ((u32*)sm->hbuf)[i] = 0;
    for (int i = tid; i < 2048; i += 256) {
        int b = i & 15, tt = i >> 4;
        sm->xs[i] = X[((size_t)(p * BSUB + b) * LSEQ + tt) * NVAR + nv];
    }
    u32 ahi[MT * KT9 * 4];
    {
        const uint4* gA = g_AhiE + ((size_t)nv * NW + w) * (MT * KT9 * 32);
        #pragma unroll
        for (int f = 0; f < MT * KT9; f++) {
            uint4 v = gA[f * 32 + lane];
            ahi[f * 4] = v.x; ahi[f * 4 + 1] = v.y; ahi[f * 4 + 2] = v.z; ahi[f * 4 + 3] = v.w;
        }
    }
    __syncthreads();
    if (tid < 32) {
        int g = tid >> 4, par = (tid >> 3) & 1, row = tid & 7;
        sm->hbuf[(g << 2) | (par << 1)][row * HSTR + 65] = 0x3F803F80u;
    }
    if (tid < 16) {
        int g = tid >> 3, row = tid & 7;
        float x = sm->xs[tid];
        unsigned short xh = f2bf(x);
        unsigned short xl = f2bf(x - bf2f(xh));
        sm->hbuf[(g << 2)][row * HSTR + 64]     = (u32)xh | ((u32)xh << 16);
        sm->hbuf[(g << 2) | 1][row * HSTR + 64] = (u32)xl;
    }
    mbar_wait(mbA, 0);
    __syncthreads();

    const int u0 = 16 * w + gid, u1 = u0 + 8;
    const float pw0 = pool_w[nv * DD + u0], pw1 = pool_w[nv * DD + u1];
    const float pb = pool_b[nv];
    float cA[2][2], cB[2][2], hA[2][2], hB[2][2];
    float accCA[2][2], accCB[2][2], pmA[2], pmB[2], psA[2], psB[2];
    #pragma unroll
    for (int ui = 0; ui < 2; ui++)
        #pragma unroll
        for (int j = 0; j < 2; j++) {
            cA[ui][j] = cB[ui][j] = 0.f;
            accCA[ui][j] = accCB[ui][j] = 0.f;
        }
    #pragma unroll
    for (int j = 0; j < 2; j++) { pmA[j] = pmB[j] = -1e30f; psA[j] = psB[j] = 0.f; }

    const uint4* aloW = sm->alo + w * (MT * KT9 * 32);
    float accA[4][4], accB[4][4];
    ZACC(accA);
    {
        const u32* hb0 = sm->hbuf[0];
        #pragma unroll
        for (int kt = 0; kt < KT9; kt++) mma_kt(aloW, hb0, ahi, accA, lane, kt);
    }

    const int TS = LSEQ - 1;
    for (int ts = 0; ts < TS; ts++) {
        int par = ts & 1;
        const u32* hbB  = sm->hbuf[4 | (par << 1)];
        const u32* hbA2 = sm->hbuf[(par ^ 1) << 1];
        u32 hibA = smem_u32(sm->hbuf[(par ^ 1) << 1]);
        u32 hibB = smem_u32(sm->hbuf[4 | ((par ^ 1) << 1)]);

        // ===== first half: GEMM_B(ts) interleaved with epilogue A(ts) =====
        ZACC(accB);
        mma_kt(aloW, hbB, ahi, accB, lane, 0);
        mma_kt(aloW, hbB, ahi, accB, lane, 1);
        gates_group(accA, cA, hA);
        mma_kt(aloW, hbB, ahi, accB, lane, 2);
        mma_kt(aloW, hbB, ahi, accB, lane, 3);
        store_group(hibA, hA, t, u0, u1);
        if (tid < 8) {
            float x = sm->xs[(ts + 1) * 16 + tid];
            unsigned short xh = f2bf(x);
            unsigned short xl = f2bf(x - bf2f(xh));
            sm->hbuf[(par ^ 1) << 1][tid * HSTR + 64]       = (u32)xh | ((u32)xh << 16);
            sm->hbuf[((par ^ 1) << 1) | 1][tid * HSTR + 64] = (u32)xl;
        }
        mma_kt(aloW, hbB, ahi, accB, lane, 4);
        mma_kt(aloW, hbB, ahi, accB, lane, 5);
        {
            float part[2];
            #pragma unroll
            for (int j = 0; j < 2; j++) part[j] = hA[0][j] * pw0 + hA[1][j] * pw1;
            #pragma unroll
            for (int off = 4; off <= 16; off <<= 1)
                #pragma unroll
                for (int j = 0; j < 2; j++)
                    part[j] += __shfl_xor_sync(0xffffffffu, part[j], off);
            if (gid == 0) { sm->sp[w][2 * t] = part[0]; sm->sp[w][2 * t + 1] = part[1]; }
        }
        mma_kt(aloW, hbB, ahi, accB, lane, 6);
        mma_kt(aloW, hbB, ahi, accB, lane, 7);
        mma_kt(aloW, hbB, ahi, accB, lane, 8);
        __syncthreads();   // bar1: h_A(ts+1 state), x, sp(A)

        // ===== second half: GEMM_A(ts+1) interleaved with accC_A + epilogue B(ts) =====
        ZACC(accA);
        mma_kt(aloW, hbA2, ahi, accA, lane, 0);
        mma_kt(aloW, hbA2, ahi, accA, lane, 1);
        #pragma unroll
        for (int j = 0; j < 2; j++) {
            float s = pb;
            #pragma unroll
            for (int ww = 0; ww < NW; ww++) s += sm->sp[ww][2 * t + j];
            float mn = fmaxf(pmA[j], s);
            float scale = __expf(pmA[j] - mn);
            float wcur  = __expf(s - mn);
            psA[j] = psA[j] * scale + wcur;
            pmA[j] = mn;
            accCA[0][j] = accCA[0][j] * scale + wcur * hA[0][j];
            accCA[1][j] = accCA[1][j] * scale + wcur * hA[1][j];
        }
        mma_kt(aloW, hbA2, ahi, accA, lane, 2);
        mma_kt(aloW, hbA2, ahi, accA, lane, 3);
        gates_group(accB, cB, hB);
        mma_kt(aloW, hbA2, ahi, accA, lane, 4);
        mma_kt(aloW, hbA2, ahi, accA, lane, 5);
        store_group(hibB, hB, t, u0, u1);
        if (tid >= 8 && tid < 16) {
            float x = sm->xs[(ts + 1) * 16 + tid];
            unsigned short xh = f2bf(x);
            unsigned short xl = f2bf(x - bf2f(xh));
            sm->hbuf[4 | ((par ^ 1) << 1)][(tid - 8) * HSTR + 64]       = (u32)xh | ((u32)xh << 16);
            sm->hbuf[4 | ((par ^ 1) << 1) | 1][(tid - 8) * HSTR + 64]   = (u32)xl;
        }
        mma_kt(aloW, hbA2, ahi, accA, lane, 6);
        {
            float part[2];
            #pragma unroll
            for (int j = 0; j < 2; j++) part[j] = hB[0][j] * pw0 + hB[1][j] * pw1;
            #pragma unroll
            for (int off = 4; off <= 16; off <<= 1)
                #pragma unroll
                for (int j = 0; j < 2; j++)
                    part[j] += __shfl_xor_sync(0xffffffffu, part[j], off);
            if (gid == 0) { sm->sp[w][8 + 2 * t] = part[0]; sm->sp[w][8 + 2 * t + 1] = part[1]; }
        }
        mma_kt(aloW, hbA2, ahi, accA, lane, 7);
        mma_kt(aloW, hbA2, ahi, accA, lane, 8);
        __syncthreads();   // bar2
        #pragma unroll
        for (int j = 0; j < 2; j++) {
            float s = pb;
            #pragma unroll
            for (int ww = 0; ww < NW; ww++) s += sm->sp[ww][8 + 2 * t + j];
            float mn = fmaxf(pmB[j], s);
            float scale = __expf(pmB[j] - mn);
            float wcur  = __expf(s - mn);
            psB[j] = psB[j] * scale + wcur;
            pmB[j] = mn;
            accCB[0][j] = accCB[0][j] * scale + wcur * hB[0][j];
            accCB[1][j] = accCB[1][j] * scale + wcur * hB[1][j];
        }
    }
    #pragma unroll
    for (int j = 0; j < 2; j++) {
        int bA = p * BSUB + 2 * t + j;
        int bB = bA + 8;
        float ivA = __fdividef(1.f, psA[j]);
        float ivB = __fdividef(1.f, psB[j]);
        g_C[((size_t)bA * NVAR + nv) * DD + u0] = accCA[0][j] * ivA;
        g_C[((size_t)bA * NVAR + nv) * DD + u1] = accCA[1][j] * ivA;
        g_C[((size_t)bB * NVAR + nv) * DD + u0] = accCB[0][j] * ivB;
        g_C[((size_t)bB * NVAR + nv) * DD + u1] = accCB[1][j] * ivB;
    }
}

// ================= MHSA =================
__global__ __launch_bounds__(128, 1) void mhsa_kernel(
    const float* __restrict__ bqkv,
    const float* __restrict__ Wo, const float* __restrict__ bo,
    float* __restrict__ out) {
    extern __shared__ __align__(16) float smf[];
    float* Cs  = smf;
    float* QKV = smf + 4352;
    float* As  = smf;
    const int b = blockIdx.x, tid = threadIdx.x;

    #pragma unroll 4
    for (int i = 0; i < 32; i++)
        Cs[tid * 34 + i] = g_C[(b * NVAR + i) * DD + tid];
    __syncthreads();

    for (int jj = 0; jj < 3; jj++) {
        int j = jj * 128 + tid;
        float bj = bqkv[j];
        u64 acc[16];
        #pragma unroll
        for (int vp = 0; vp < 16; vp++) acc[vp] = pack2(bj, bj);
        #pragma unroll 2
        for (int k = 0; k < DD; k++) {
            float wv = g_WqkvT[k * 384 + j];
            u64 ww = pack2(wv, wv);
            const u64* crow = (const u64*)&Cs[k * 34];
            #pragma unroll
            for (int vp = 0; vp < 16; vp++) acc[vp] = ffma2(ww, crow[vp], acc[vp]);
        }
        #pragma unroll
        for (int vp = 0; vp < 16; vp++) {
            float a0, a1; unpack2(acc[vp], a0, a1);
            QKV[(2 * vp)     * 385 + j] = a0;
            QKV[(2 * vp + 1) * 385 + j] = a1;
        }
    }
    __syncthreads();
    {
        int h = tid >> 5, i = tid & 31;
        float q[32];
        #pragma unroll
        for (int d = 0; d < 32; d++) q[d] = QKV[i * 385 + h * 32 + d];
        float s[32];
        #pragma unroll
        for (int j = 0; j < 32; j++) {
            float a = 0.f;
            #pragma unroll
            for (int d = 0; d < 32; d++) a += q[d] * QKV[j * 385 + 128 + h * 32 + d];
            s[j] = a * 0.17677669529663687f;
        }
        float mx = s[0];
        #pragma unroll
        for (int j = 1; j < 32; j++) mx = fmaxf(mx, s[j]);
        float sum = 0.f;
        #pragma unroll
        for (int j = 0; j < 32; j++) { s[j] = __expf(s[j] - mx); sum += s[j]; }
        float inv = __fdividef(1.f, sum);
        float A[32];
        #pragma unroll
        for (int d = 0; d < 32; d++) A[d] = 0.f;
        #pragma unroll
        for (int j = 0; j < 32; j++) {
            float aj = s[j] * inv;
            #pragma unroll
            for (int d = 0; d < 32; d++) A[d] += aj * QKV[j * 385 + 256 + h * 32 + d];
        }
        #pragma unroll
        for (int d = 0; d < 32; d++) As[i * 129 + h * 32 + d] = A[d];
    }
    __syncthreads();
    {
        int v = tid & 31, uc = tid >> 5;
        for (int mm = 0; mm < 32; mm++) {
            int u = uc * 32 + mm;
            float a = bo[u];
            #pragma unroll 4
            for (int d = 0; d < DD; d++) a += As[v * 129 + d] * Wo[u * DD + d];
            g_Cstar[(b * NVAR + v) * DD + u] = a;
            out[CSTAR_OFF + (b * NVAR + v) * DD + u] = a;
        }
    }
}

// ================= decoder =================
__global__ __launch_bounds__(256, 1) void dec_kernel(
    const float* __restrict__ ihW, const float* __restrict__ ihB,
    const float* __restrict__ icW, const float* __restrict__ icB,
    const float* __restrict__ outW, const float* __restrict__ outB,
    float* __restrict__ out) {
    extern __shared__ __align__(16) char smraw[];
    SmemMMA* sm = (SmemMMA*)smraw;
    const int nv = blockIdx.y, p = blockIdx.x;
    const int tid = threadIdx.x, lane = tid & 31, w = tid >> 5;
    const int gid = lane >> 2, t = lane & 3;
    u32 mbA = smem_u32(&sm->mbar[0]);

    if (tid == 0) {
        mbar_init(mbA, 1);
        mbar_expect_tx(mbA, 147456);
        const char* src = (const char*)(g_AloD + (size_t)nv * (NW * MT * KT9 * 32));
        bulk_copy(src,          sm->alo,                73728, mbA);
        bulk_copy(src + 73728, (char*)sm->alo + 73728,  73728, mbA);
    }
    for (int i = tid; i < 8 * HBUF_W; i += 256) ((u32*)sm->hbuf)[i] = 0;
    for (int i = tid; i < 2048; i += 256) {
        int b = i & 15, k = i >> 4;
        sm->xs[i] = g_Cstar[((size_t)(p * BSUB + b) * NVAR + nv) * DD + k];
    }
    u32 ahi[MT * KT9 * 4];
    {
        const uint4* gA = g_AhiD + ((size_t)nv * NW + w) * (MT * KT9 * 32);
        #pragma unroll
        for (int f = 0; f < MT * KT9; f++) {
            uint4 v = gA[f * 32 + lane];
            ahi[f * 4] = v.x; ahi[f * 4 + 1] = v.y; ahi[f * 4 + 2] = v.z; ahi[f * 4 + 3] = v.w;
        }
    }
    __syncthreads();
    if (tid < 32) {
        int g = tid >> 4, par = (tid >> 3) & 1, row = tid & 7;
        sm->hbuf[(g << 2) | (par << 1)][row * HSTR + 65] = 0x3F803F80u;
    }

    const int u0 = 16 * w + gid, u1 = u0 + 8;
    int gcols[4] = {2 * t, 2 * t + 1, 8 + 2 * t, 8 + 2 * t + 1};

    float cA[2][2], cB[2][2], hA[2][2], hB[2][2];
    {
        float ah0[4], ah1[4], ac0[4], ac1[4];
        float bh0 = ihB[nv * DD + u0], bh1 = ihB[nv * DD + u1];
        float bc0 = icB[nv * DD + u0], bc1 = icB[nv * DD + u1];
        #pragma unroll
        for (int j = 0; j < 4; j++) { ah0[j] = bh0; ah1[j] = bh1; ac0[j] = bc0; ac1[j] = bc1; }
        const float* wh0 = ihW + ((size_t)nv * DD + u0) * DD;
        const float* wh1 = ihW + ((size_t)nv * DD + u1) * DD;
        const float* wc0 = icW + ((size_t)nv * DD + u0) * DD;
        const float* wc1 = icW + ((size_t)nv * DD + u1) * DD;
        #pragma unroll 2
        for (int k = 0; k < DD; k++) {
            float a0 = wh0[k], a1 = wh1[k], b0 = wc0[k], b1 = wc1[k];
            #pragma unroll
            for (int j = 0; j < 4; j++) {
                float cv = sm->xs[k * 16 + gcols[j]];
                ah0[j] += a0 * cv; ah1[j] += a1 * cv;
                ac0[j] += b0 * cv; ac1[j] += b1 * cv;
            }
        }
        #pragma unroll
        for (int j = 0; j < 2; j++) {
            hA[0][j] = ftanhf(ah0[j]);     hA[1][j] = ftanhf(ah1[j]);
            cA[0][j] = ftanhf(ac0[j]);     cA[1][j] = ftanhf(ac1[j]);
            hB[0][j] = ftanhf(ah0[2 + j]); hB[1][j] = ftanhf(ah1[2 + j]);
            cB[0][j] = ftanhf(ac0[2 + j]); cB[1][j] = ftanhf(ac1[2 + j]);
        }
    }
    __syncthreads();
    store_group(smem_u32(sm->hbuf[0]), hA, t, u0, u1);
    store_group(smem_u32(sm->hbuf[4]), hB, t, u0, u1);
    mbar_wait(mbA, 0);
    __syncthreads();

    const float wo0 = outW[nv * DD + u0], wo1 = outW[nv * DD + u1];
    const float ob = outB[nv];
    const uint4* aloW = sm->alo + w * (MT * KT9 * 32);
    const int b_row0 = p * BSUB;

    float accA[4][4], accB[4][4];
    ZACC(accA);
    {
        const u32* hb0 = sm->hbuf[0];
        #pragma unroll
        for (int kt = 0; kt < KT9; kt++) mma_kt(aloW, hb0, ahi, accA, lane, kt);
    }

    for (int l = 0; l < LSEQ; l++) {
        int par = l & 1;
        const u32* hbB  = sm->hbuf[4 | (par << 1)];
        const u32* hbA2 = sm->hbuf[(par ^ 1) << 1];
        u32 hibA = smem_u32(sm->hbuf[(par ^ 1) << 1]);
        u32 hibB = smem_u32(sm->hbuf[4 | ((par ^ 1) << 1)]);

        // ===== first half: GEMM_B(l) interleaved with epilogue A(l) =====
        ZACC(accB);
        mma_kt(aloW, hbB, ahi, accB, lane, 0);
        mma_kt(aloW, hbB, ahi, accB, lane, 1);
        gates_group(accA, cA, hA);
        mma_kt(aloW, hbB, ahi, accB, lane, 2);
        mma_kt(aloW, hbB, ahi, accB, lane, 3);
        store_group(hibA, hA, t, u0, u1);
        mma_kt(aloW, hbB, ahi, accB, lane, 4);
        mma_kt(aloW, hbB, ahi, accB, lane, 5);
        {
            float part[2];
            #pragma unroll
            for (int j = 0; j < 2; j++) part[j] = hA[0][j] * wo0 + hA[1][j] * wo1;
            #pragma unroll
            for (int off = 4; off <= 16; off <<= 1)
                #pragma unroll
                for (int j = 0; j < 2; j++)
                    part[j] += __shfl_xor_sync(0xffffffffu, part[j], off);
            if (gid == 0) { sm->sp[w][2 * t] = part[0]; sm->sp[w][2 * t + 1] = part[1]; }
        }
        mma_kt(aloW, hbB, ahi, accB, lane, 6);
        mma_kt(aloW, hbB, ahi, accB, lane, 7);
        mma_kt(aloW, hbB, ahi, accB, lane, 8);
        __syncthreads();   // bar1

        // ===== second half: GEMM_A(l+1) interleaved with out-A + epilogue B(l) =====
        ZACC(accA);
        mma_kt(aloW, hbA2, ahi, accA, lane, 0);
        mma_kt(aloW, hbA2, ahi, accA, lane, 1);
        if (tid < 8) {
            float O = ob;
            #pragma unroll
            for (int ww = 0; ww < NW; ww++) O += sm->sp[ww][tid];
            int b = b_row0 + tid;
            if (l < LSEQ - 1) out[((size_t)b * (LSEQ - 1) + l) * NVAR + nv] = O;
            else              out[PRED_OFF + b * NVAR + nv] = O;
        }
        mma_kt(aloW, hbA2, ahi, accA, lane, 2);
        mma_kt(aloW, hbA2, ahi, accA, lane, 3);
        gates_group(accB, cB, hB);
        mma_kt(aloW, hbA2, ahi, accA, lane, 4);
        mma_kt(aloW, hbA2, ahi, accA, lane, 5);
        store_group(hibB, hB, t, u0, u1);
        mma_kt(aloW, hbA2, ahi, accA, lane, 6);
        {
            float part[2];
            #pragma unroll
            for (int j = 0; j < 2; j++) part[j] = hB[0][j] * wo0 + hB[1][j] * wo1;
            #pragma unroll
            for (int off = 4; off <= 16; off <<= 1)
                #pragma unroll
                for (int j = 0; j < 2; j++)
                    part[j] += __shfl_xor_sync(0xffffffffu, part[j], off);
            if (gid == 0) { sm->sp[w][8 + 2 * t] = part[0]; sm->sp[w][8 + 2 * t + 1] = part[1]; }
        }
        mma_kt(aloW, hbA2, ahi, accA, lane, 7);
        mma_kt(aloW, hbA2, ahi, accA, lane, 8);
        __syncthreads();   // bar2
        if (tid >= 8 && tid < 16) {
            float O = ob;
            #pragma unroll
            for (int ww = 0; ww < NW; ww++) O += sm->sp[ww][tid];
            int b = b_row0 + tid;
            if (l < LSEQ - 1) out[((size_t)b * (LSEQ - 1) + l) * NVAR + nv] = O;
            else              out[PRED_OFF + b * NVAR + nv] = O;
        }
    }
}

// ---------------- launch ----------------
extern "C" void kernel_launch(void* const* d_in, const int* in_sizes, int n_in,
                              void* d_out, int out_size) {
    (void)in_sizes; (void)n_in; (void)out_size;
    const float* X        = (const float*)d_in[0];
    const float* enc_Wih  = (const float*)d_in[1];
    const float* enc_Whh  = (const float*)d_in[2];
    const float* enc_bih  = (const float*)d_in[3];
    const float* enc_bhh  = (const float*)d_in[4];
    const float* pool_w   = (const float*)d_in[5];
    const float* pool_b   = (const float*)d_in[6];
    const float* Wqkv     = (const float*)d_in[7];
    const float* bqkv     = (const float*)d_in[8];
    const float* Wo       = (const float*)d_in[9];
    const float* bo       = (const float*)d_in[10];
    const float* dec_ih_W = (const float*)d_in[11];
    const float* dec_ih_b = (const float*)d_in[12];
    const float* dec_ic_W = (const float*)d_in[13];
    const float* dec_ic_b = (const float*)d_in[14];
    const float* dec_Wih  = (const float*)d_in[15];
    const float* dec_Whh  = (const float*)d_in[16];
    const float* dec_bih  = (const float*)d_in[17];
    const float* dec_bhh  = (const float*)d_in[18];
    const float* dec_out_W= (const float*)d_in[19];
    const float* dec_out_b= (const float*)d_in[20];
    float* out = (float*)d_out;

    static int attr_set = 0;
    if (!attr_set) {
        cudaFuncSetAttribute(mhsa_kernel, cudaFuncAttributeMaxDynamicSharedMemorySize, 66688);
        cudaFuncSetAttribute(enc_kernel,  cudaFuncAttributeMaxDynamicSharedMemorySize, SMEM_MMA);
        cudaFuncSetAttribute(dec_kernel,  cudaFuncAttributeMaxDynamicSharedMemorySize, SMEM_MMA);
        attr_set = 1;
    }

    uint4 *pAhiE, *pAloE, *pAhiD, *pAloD; float* pWqkvT;
    cudaGetSymbolAddress((void**)&pAhiE, g_AhiE);
    cudaGetSymbolAddress((void**)&pAloE, g_AloE);
    cudaGetSymbolAddress((void**)&pAhiD, g_AhiD);
    cudaGetSymbolAddress((void**)&pAloD, g_AloD);
    cudaGetSymbolAddress((void**)&pWqkvT, g_WqkvT);

    pack_w<<<1152, 256>>>(enc_Whh, enc_Wih, enc_bih, enc_bhh, pAhiE, pAloE, 1);
    pack_w<<<1152, 256>>>(dec_Whh, dec_Wih, dec_bih, dec_bhh, pAhiD, pAloD, 0);
    transpose_kernel<<<dim3(4, 12, 1), dim3(32, 8)>>>(Wqkv, pWqkvT, 384, 128);

    enc_kernel<<<dim3(PSPLIT, NVAR), 256, SMEM_MMA>>>(X, pool_w, pool_b);
    mhsa_kernel<<<BATCH, 128, 66688>>>(bqkv, Wo, bo, out);
    dec_kernel<<<dim3(PSPLIT, NVAR), 256, SMEM_MMA>>>(dec_ih_W, dec_ih_b, dec_ic_W, dec_ic_b,
                                                      dec_out_W, dec_out_b, out);
}